// round 5
// baseline (speedup 1.0000x reference)
#include <cuda_runtime.h>
#include <cstdint>

typedef unsigned long long ull;

#define T_LEN  16384
#define BATCH  10
#define DDIM   3
#define HDIM   4
#define NITER  10
#define NCHAIN (NITER*BATCH)   // 100
#define NGATE  16
#define DIST   16              // cp.async ring depth (steps)

// ---------------- device scratch (static: no allocation allowed) ----------------
__device__ float g_W2[NITER*DDIM*NGATE];                    // zx & 0.5-scale folded: [iter][d][k]
__device__ float g_U2[NITER*HDIM*NGATE];                    // zh & 0.5-scale folded: [iter][j][k]
__device__ float g_xproj[(size_t)NCHAIN*T_LEN*NGATE];       // 104.9 MB  [chain][t][k]
__device__ float g_scratch[(size_t)T_LEN*NCHAIN*12];        // 78.6 MB   [t][chain][o0..3,h0..3,c0..3]

// ---------------- helpers ----------------
__device__ __forceinline__ float tanh_ap(float x) {
    float y; asm("tanh.approx.f32 %0, %1;" : "=f"(y) : "f"(x)); return y;
}
__device__ __forceinline__ ull pack2(float lo, float hi) {
    ull r; asm("mov.b64 %0, {%1, %2};" : "=l"(r) : "f"(lo), "f"(hi)); return r;
}
__device__ __forceinline__ ull splat2(float x) {
    ull r; asm("mov.b64 %0, {%1, %1};" : "=l"(r) : "f"(x)); return r;
}
__device__ __forceinline__ ull ffma2(ull a, ull b, ull c) {
    ull d; asm("fma.rn.f32x2 %0, %1, %2, %3;" : "=l"(d) : "l"(a), "l"(b), "l"(c)); return d;
}
__device__ __forceinline__ float lo2(ull v) { return __uint_as_float((unsigned)(v)); }
__device__ __forceinline__ float hi2(ull v) { return __uint_as_float((unsigned)(v >> 32)); }

// ---------------- 1) fold masks/scales into W2, U2 ----------------
// gate order k = gate*4 + unit, gates: 0=i 1=f 2=o 3=g. Scale 0.5 for i,f,o
// (sigmoid(a) = 0.5*tanh(a/2)+0.5), 1.0 for g.
__global__ void setup_k(const float* __restrict__ zx, const float* __restrict__ zh,
                        const float* __restrict__ Wi, const float* __restrict__ Ui,
                        const float* __restrict__ Wf, const float* __restrict__ Uf,
                        const float* __restrict__ Wo, const float* __restrict__ Uo,
                        const float* __restrict__ Wg, const float* __restrict__ Ug) {
    int tid = blockIdx.x * blockDim.x + threadIdx.x;
    if (tid < NITER*DDIM*NGATE) {                  // W2: zx * W * scale
        int k = tid % NGATE, d = (tid / NGATE) % DDIM, it = tid / (NGATE*DDIM);
        int gate = k >> 2, u = k & 3;
        const float* W = (gate == 0) ? Wi : (gate == 1) ? Wf : (gate == 2) ? Wo : Wg;
        float s = (gate < 3) ? 0.5f : 1.0f;
        g_W2[tid] = zx[it*DDIM + d] * W[d*HDIM + u] * s;
    }
    if (tid < NITER*HDIM*NGATE) {                  // U2: zh * U * scale
        int k = tid % NGATE, j = (tid / NGATE) % HDIM, it = tid / (NGATE*HDIM);
        int gate = k >> 2, u = k & 3;
        const float* U = (gate == 0) ? Ui : (gate == 1) ? Uf : (gate == 2) ? Uo : Ug;
        float s = (gate < 3) ? 0.5f : 1.0f;
        g_U2[tid] = zh[it*HDIM + j] * U[j*HDIM + u] * s;
    }
}

// ---------------- 2) precompute xproj[chain][t][16] ----------------
__global__ void __launch_bounds__(256) xproj_k(const float* __restrict__ x) {
    int tid = blockIdx.x * blockDim.x + threadIdx.x;     // chain-major, t fastest
    int t = tid % T_LEN;
    int chain = tid / T_LEN;
    if (chain >= NCHAIN) return;
    int it = chain / BATCH, b = chain % BATCH;
    const float* xr = x + ((size_t)t*BATCH + b)*DDIM;
    float x0 = xr[0], x1 = xr[1], x2 = xr[2];
    const float* W = g_W2 + it*DDIM*NGATE;
    float v[NGATE];
#pragma unroll
    for (int k = 0; k < NGATE; k++)
        v[k] = x0*W[k] + x1*W[NGATE + k] + x2*W[2*NGATE + k];
    float4* out = (float4*)(g_xproj + ((size_t)chain*T_LEN + t)*NGATE);
    out[0] = make_float4(v[0],  v[1],  v[2],  v[3]);
    out[1] = make_float4(v[4],  v[5],  v[6],  v[7]);
    out[2] = make_float4(v[8],  v[9],  v[10], v[11]);
    out[3] = make_float4(v[12], v[13], v[14], v[15]);
}

// ---------------- 3) the serial recurrence: one chain per warp/SMSP ----------------
__global__ void __launch_bounds__(32, 1) lstm_k() {
    __shared__ float4 ring[DIST*4];                 // 16 steps x 64B
    if (threadIdx.x != 0) return;
    const int chain = blockIdx.x;

    // per-chain U2 constants as packed f32x2 pairs (zh & scale already folded)
    ull u[HDIM][8];
    {
        const float* Ub = g_U2 + (chain / BATCH)*HDIM*NGATE;
#pragma unroll
        for (int j = 0; j < HDIM; j++)
#pragma unroll
            for (int p = 0; p < 8; p++)
                u[j][p] = pack2(Ub[j*NGATE + 2*p], Ub[j*NGATE + 2*p + 1]);
    }

    const float* xp = g_xproj + (size_t)chain*T_LEN*NGATE;
    unsigned rbase = (unsigned)__cvta_generic_to_shared(ring);

    // prologue: prefetch DIST steps
    for (int p = 0; p < DIST; p++) {
        const float* src = xp + (size_t)p*NGATE;
        unsigned dst = rbase + p*64u;
#pragma unroll
        for (int q = 0; q < 4; q++)
            asm volatile("cp.async.cg.shared.global [%0], [%1], 16;" :: "r"(dst + q*16u), "l"(src + q*4));
        asm volatile("cp.async.commit_group;");
    }

    float h[HDIM] = {0.f, 0.f, 0.f, 0.f};
    float c[HDIM] = {0.f, 0.f, 0.f, 0.f};
    float* sc = g_scratch + (size_t)chain*12;

    for (int t = 0; t < T_LEN; t++) {
        asm volatile("cp.async.wait_group %0;" :: "n"(DIST-2) : "memory");
        int slot = t & (DIST-1);
        float4 xa = ring[slot*4+0], xb = ring[slot*4+1], xc = ring[slot*4+2], xd = ring[slot*4+3];

        // refill this slot with step t+DIST (after consuming it)
        if (t + DIST < T_LEN) {
            const float* src = xp + (size_t)(t + DIST)*NGATE;
            unsigned dst = rbase + slot*64u;
#pragma unroll
            for (int q = 0; q < 4; q++)
                asm volatile("cp.async.cg.shared.global [%0], [%1], 16;" :: "r"(dst + q*16u), "l"(src + q*4));
        }
        asm volatile("cp.async.commit_group;");

        // gates = xp + h @ U2   (8 packed accumulators = 16 gate pre-acts)
        ull a0 = pack2(xa.x, xa.y), a1 = pack2(xa.z, xa.w);
        ull a2 = pack2(xb.x, xb.y), a3 = pack2(xb.z, xb.w);
        ull a4 = pack2(xc.x, xc.y), a5 = pack2(xc.z, xc.w);
        ull a6 = pack2(xd.x, xd.y), a7 = pack2(xd.z, xd.w);
#pragma unroll
        for (int j = 0; j < HDIM; j++) {
            ull s = splat2(h[j]);
            a0 = ffma2(s, u[j][0], a0);  a1 = ffma2(s, u[j][1], a1);
            a2 = ffma2(s, u[j][2], a2);  a3 = ffma2(s, u[j][3], a3);
            a4 = ffma2(s, u[j][4], a4);  a5 = ffma2(s, u[j][5], a5);
            a6 = ffma2(s, u[j][6], a6);  a7 = ffma2(s, u[j][7], a7);
        }
        // activations: i,f,o via sigmoid(x)=0.5*tanh(x/2)+0.5 (scale folded), g via tanh
        float i0 = fmaf(tanh_ap(lo2(a0)), 0.5f, 0.5f), i1 = fmaf(tanh_ap(hi2(a0)), 0.5f, 0.5f);
        float i2 = fmaf(tanh_ap(lo2(a1)), 0.5f, 0.5f), i3 = fmaf(tanh_ap(hi2(a1)), 0.5f, 0.5f);
        float f0 = fmaf(tanh_ap(lo2(a2)), 0.5f, 0.5f), f1 = fmaf(tanh_ap(hi2(a2)), 0.5f, 0.5f);
        float f2 = fmaf(tanh_ap(lo2(a3)), 0.5f, 0.5f), f3 = fmaf(tanh_ap(hi2(a3)), 0.5f, 0.5f);
        float o0 = fmaf(tanh_ap(lo2(a4)), 0.5f, 0.5f), o1 = fmaf(tanh_ap(hi2(a4)), 0.5f, 0.5f);
        float o2 = fmaf(tanh_ap(lo2(a5)), 0.5f, 0.5f), o3 = fmaf(tanh_ap(hi2(a5)), 0.5f, 0.5f);
        float g0 = tanh_ap(lo2(a6)), g1 = tanh_ap(hi2(a6));
        float g2 = tanh_ap(lo2(a7)), g3 = tanh_ap(hi2(a7));

        c[0] = fmaf(f0, c[0], i0*g0);  c[1] = fmaf(f1, c[1], i1*g1);
        c[2] = fmaf(f2, c[2], i2*g2);  c[3] = fmaf(f3, c[3], i3*g3);
        float t0 = tanh_ap(c[0]), t1 = tanh_ap(c[1]), t2 = tanh_ap(c[2]), t3 = tanh_ap(c[3]);
        h[0] = o0*t0;  h[1] = o1*t1;  h[2] = o2*t2;  h[3] = o3*t3;

        float4* st = (float4*)(sc + (size_t)t*(NCHAIN*12));
        st[0] = make_float4(o0, o1, o2, o3);
        st[1] = make_float4(h[0], h[1], h[2], h[3]);
        st[2] = make_float4(c[0], c[1], c[2], c[3]);
    }
}

// ---------------- 4) deterministic mean over the 10 MC iterations ----------------
__global__ void __launch_bounds__(256) reduce_k(float* __restrict__ out) {
    int tid = blockIdx.x * blockDim.x + threadIdx.x;
    if (tid >= T_LEN*BATCH*12) return;
    int t = tid / (BATCH*12);
    int r = tid % (BATCH*12);
    int b = r / 12, comp = r % 12;
    const float* base = g_scratch + ((size_t)t*NCHAIN + b)*12 + comp;
    float s = 0.f;
#pragma unroll
    for (int it = 0; it < NITER; it++) s += base[(size_t)it*BATCH*12];
    int tensor = comp >> 2, unit = comp & 3;
    out[(size_t)tensor*T_LEN*BATCH*HDIM + ((size_t)t*BATCH + b)*HDIM + unit] = 0.1f*s;
}

// ---------------- launch ----------------
extern "C" void kernel_launch(void* const* d_in, const int* in_sizes, int n_in,
                              void* d_out, int out_size) {
    const float* input = (const float*)d_in[0];
    const float* zx    = (const float*)d_in[1];
    const float* zh    = (const float*)d_in[2];
    const float* Wi    = (const float*)d_in[3];
    const float* Ui    = (const float*)d_in[4];
    const float* Wf    = (const float*)d_in[5];
    const float* Uf    = (const float*)d_in[6];
    const float* Wo    = (const float*)d_in[7];
    const float* Uo    = (const float*)d_in[8];
    const float* Wg    = (const float*)d_in[9];
    const float* Ug    = (const float*)d_in[10];
    float* out = (float*)d_out;

    setup_k<<<1, 1024>>>(zx, zh, Wi, Ui, Wf, Uf, Wo, Uo, Wg, Ug);
    xproj_k<<<(NCHAIN*T_LEN + 255)/256, 256>>>(input);
    lstm_k<<<NCHAIN, 32>>>();
    reduce_k<<<(T_LEN*BATCH*12 + 255)/256, 256>>>(out);
}

// round 6
// speedup vs baseline: 1.2852x; 1.2852x over previous
#include <cuda_runtime.h>
#include <cstdint>

#define T_LEN  16384
#define BATCH  10
#define DDIM   3
#define HDIM   4
#define NITER  10
#define NCHAIN (NITER*BATCH)   // 100
#define NGATE  16

// ---------------- device scratch (static: no allocation allowed) ----------------
__device__ float g_W2[NITER*DDIM*NGATE];                // zx & 0.5-scale folded: [iter][d][k]
__device__ float g_U2[NITER*HDIM*NGATE];                // zh & 0.5-scale folded: [iter][j][k]
__device__ float g_xproj[(size_t)NCHAIN*T_LEN*NGATE];   // 104.9 MB  [chain][t][k]
__device__ float g_scratch[(size_t)T_LEN*NCHAIN*16];    // 104.9 MB  [t][chain][u][4] = (o,h,c,pad)

// ---------------- helpers ----------------
__device__ __forceinline__ float tanh_ap(float x) {
    float y; asm("tanh.approx.f32 %0, %1;" : "=f"(y) : "f"(x)); return y;
}

// ---------------- 1) fold masks/scales into W2, U2 ----------------
// gate order k = gate*4 + unit, gates: 0=i 1=f 2=o 3=g. Scale 0.5 for i,f,o
// (sigmoid(a) = 0.5*tanh(a/2)+0.5), 1.0 for g.
__global__ void setup_k(const float* __restrict__ zx, const float* __restrict__ zh,
                        const float* __restrict__ Wi, const float* __restrict__ Ui,
                        const float* __restrict__ Wf, const float* __restrict__ Uf,
                        const float* __restrict__ Wo, const float* __restrict__ Uo,
                        const float* __restrict__ Wg, const float* __restrict__ Ug) {
    int tid = blockIdx.x * blockDim.x + threadIdx.x;
    if (tid < NITER*DDIM*NGATE) {                  // W2: zx * W * scale
        int k = tid % NGATE, d = (tid / NGATE) % DDIM, it = tid / (NGATE*DDIM);
        int gate = k >> 2, u = k & 3;
        const float* W = (gate == 0) ? Wi : (gate == 1) ? Wf : (gate == 2) ? Wo : Wg;
        float s = (gate < 3) ? 0.5f : 1.0f;
        g_W2[tid] = zx[it*DDIM + d] * W[d*HDIM + u] * s;
    }
    if (tid < NITER*HDIM*NGATE) {                  // U2: zh * U * scale
        int k = tid % NGATE, j = (tid / NGATE) % HDIM, it = tid / (NGATE*HDIM);
        int gate = k >> 2, u = k & 3;
        const float* U = (gate == 0) ? Ui : (gate == 1) ? Uf : (gate == 2) ? Uo : Ug;
        float s = (gate < 3) ? 0.5f : 1.0f;
        g_U2[tid] = zh[it*HDIM + j] * U[j*HDIM + u] * s;
    }
}

// ---------------- 2) precompute xproj[chain][t][16] ----------------
__global__ void __launch_bounds__(256) xproj_k(const float* __restrict__ x) {
    int tid = blockIdx.x * blockDim.x + threadIdx.x;     // chain-major, t fastest
    int t = tid % T_LEN;
    int chain = tid / T_LEN;
    if (chain >= NCHAIN) return;
    int it = chain / BATCH, b = chain % BATCH;
    const float* xr = x + ((size_t)t*BATCH + b)*DDIM;
    float x0 = xr[0], x1 = xr[1], x2 = xr[2];
    const float* W = g_W2 + it*DDIM*NGATE;
    float v[NGATE];
#pragma unroll
    for (int k = 0; k < NGATE; k++)
        v[k] = x0*W[k] + x1*W[NGATE + k] + x2*W[2*NGATE + k];
    float4* out = (float4*)(g_xproj + ((size_t)chain*T_LEN + t)*NGATE);
    out[0] = make_float4(v[0],  v[1],  v[2],  v[3]);
    out[1] = make_float4(v[4],  v[5],  v[6],  v[7]);
    out[2] = make_float4(v[8],  v[9],  v[10], v[11]);
    out[3] = make_float4(v[12], v[13], v[14], v[15]);
}

// ---------------- 3) serial recurrence: 16 lanes per chain, gates on lanes ----------------
// lane k = gate*4 + unit; lanes 0-3 additionally own unit u (c,h state).
// Per step: 2 MUFU instructions total (16 gate tanh + 4 cell tanh), ~5 FFMA,
// 7 shfl. Latency-bound ~115 cyc/step instead of issue-bound 282.
__global__ void __launch_bounds__(16, 1) lstm_k() {
    const int lane  = threadIdx.x;      // 0..15
    const int chain = blockIdx.x;
    const int u = lane & 3;
    const unsigned FULL = 0xFFFFu;

    // per-lane U column (zh mask & sigmoid half-scale already folded)
    const float* Ub = g_U2 + (chain / BATCH)*HDIM*NGATE;
    const float u0 = Ub[0*NGATE + lane];
    const float u1 = Ub[1*NGATE + lane];
    const float u2 = Ub[2*NGATE + lane];
    const float u3 = Ub[3*NGATE + lane];

    const float* xp = g_xproj + (size_t)chain*T_LEN*NGATE + lane;
    float* sc = g_scratch + ((size_t)chain*4 + u)*4;     // [t][chain][u][4]

    float h = 0.f, c = 0.f;

    // 8-deep per-lane register prefetch pipeline for xproj (1 coalesced 64B LDG/step)
    float xbuf[8];
#pragma unroll
    for (int p = 0; p < 8; p++) xbuf[p] = xp[(size_t)p*NGATE];

    for (int t = 0; t < T_LEN; t += 8) {
#pragma unroll
        for (int p = 0; p < 8; p++) {
            float xv = xbuf[p];
            int nf = t + 8 + p; nf = (nf < T_LEN) ? nf : (T_LEN - 1);
            xbuf[p] = xp[(size_t)nf*NGATE];              // ~960 cyc of lookahead

            // broadcast h (lanes 0-3 own h_u)
            float h0 = __shfl_sync(FULL, h, 0, 16);
            float h1 = __shfl_sync(FULL, h, 1, 16);
            float h2 = __shfl_sync(FULL, h, 2, 16);
            float h3 = __shfl_sync(FULL, h, 3, 16);

            // gate pre-activation a_k = xp_k + sum_j h_j * U2[j][k]  (tree, depth 12)
            float pa = fmaf(h0, u0, xv);
            float pb = fmaf(h3, u3, h2*u2);
            pa = fmaf(h1, u1, pa);
            float a = pa + pb;

            float tv = tanh_ap(a);                       // 1 MUFU: all 16 gates

            // gather the other three gates for unit u
            float tf = __shfl_sync(FULL, tv,  4 + u, 16);
            float to = __shfl_sync(FULL, tv,  8 + u, 16);
            float tg = __shfl_sync(FULL, tv, 12 + u, 16);

            // sigmoid(x) = 0.5*tanh(x/2)+0.5 (the /2 is folded into W2/U2)
            float iv = fmaf(tv, 0.5f, 0.5f);             // own lane holds t_i[u]
            float fv = fmaf(tf, 0.5f, 0.5f);
            float ov = fmaf(to, 0.5f, 0.5f);

            c = fmaf(fv, c, iv*tg);
            float tc = tanh_ap(c);                       // 1 MUFU: 4 cells
            h = ov*tc;

            if (lane < 4) {
                float4* st = (float4*)(sc + (size_t)(t + p)*(NCHAIN*16));
                *st = make_float4(ov, h, c, tc);         // one STG.128, off critical path
            }
        }
    }
}

// ---------------- 4) deterministic mean over the 10 MC iterations ----------------
__global__ void __launch_bounds__(256) reduce_k(float* __restrict__ out) {
    int tid = blockIdx.x * blockDim.x + threadIdx.x;
    if (tid >= T_LEN*BATCH*HDIM) return;
    int u = tid & 3;
    int b = (tid >> 2) % BATCH;
    int t = tid / (BATCH*HDIM);
    const float4* base = (const float4*)g_scratch + (size_t)t*NCHAIN*4 + b*4 + u;
    float so = 0.f, sh = 0.f, scc = 0.f;
#pragma unroll
    for (int it = 0; it < NITER; it++) {
        float4 v = base[(size_t)it*BATCH*4];             // chain = it*BATCH + b
        so += v.x; sh += v.y; scc += v.z;
    }
    size_t o_idx = ((size_t)t*BATCH + b)*HDIM + u;
    const size_t TEN = (size_t)T_LEN*BATCH*HDIM;
    out[o_idx]         = 0.1f*so;
    out[TEN + o_idx]   = 0.1f*sh;
    out[2*TEN + o_idx] = 0.1f*scc;
}

// ---------------- launch ----------------
extern "C" void kernel_launch(void* const* d_in, const int* in_sizes, int n_in,
                              void* d_out, int out_size) {
    const float* input = (const float*)d_in[0];
    const float* zx    = (const float*)d_in[1];
    const float* zh    = (const float*)d_in[2];
    const float* Wi    = (const float*)d_in[3];
    const float* Ui    = (const float*)d_in[4];
    const float* Wf    = (const float*)d_in[5];
    const float* Uf    = (const float*)d_in[6];
    const float* Wo    = (const float*)d_in[7];
    const float* Uo    = (const float*)d_in[8];
    const float* Wg    = (const float*)d_in[9];
    const float* Ug    = (const float*)d_in[10];
    float* out = (float*)d_out;

    setup_k<<<1, 1024>>>(zx, zh, Wi, Ui, Wf, Uf, Wo, Uo, Wg, Ug);
    xproj_k<<<(NCHAIN*T_LEN + 255)/256, 256>>>(input);
    lstm_k<<<NCHAIN, 16>>>();
    reduce_k<<<(T_LEN*BATCH*HDIM + 255)/256, 256>>>(out);
}